// round 16
// baseline (speedup 1.0000x reference)
#include <cuda_runtime.h>
#include <cuda_fp16.h>
#include <math.h>
#include <stdint.h>

// ---------------- problem constants ----------------
#define S_TOK   16384          // B*N
#define DMODEL  1024
#define NEXP    8
#define HFFN    4096
#define CAP     2560           // int(S*1.25/E)
#define GATE_BLOCKS (S_TOK/8)

// ---------------- device scratch (allocation-free rule) ----------------
__device__ __half g_bufh[NEXP * CAP * DMODEL];            // 42 MB  dispatch fp16
__device__ __half g_hh  [(size_t)NEXP * CAP * HFFN];      // 168 MB hidden fp16
__device__ __half g_w1h [(size_t)NEXP * HFFN * DMODEL];   // 67 MB  W1^T [E][H][D]
__device__ __half g_w2h [(size_t)NEXP * DMODEL * HFFN];   // 67 MB  W2^T [E][D][H]
__device__ float g_gate1[S_TOK];
__device__ float g_gate2[S_TOK];
__device__ int   g_idx1[S_TOK];
__device__ int   g_idx2[S_TOK];
__device__ int   g_pos1[S_TOK];
__device__ int   g_pos2[S_TOK];      // RAW top-2 prefix (used1 added in dispatch)
__device__ float g_partial[GATE_BLOCKS * NEXP];
__device__ int   g_cnt1[NEXP];
__device__ int   g_slot_tok[NEXP * CAP];                  // token id or -1
__device__ float g_slot_w  [NEXP * CAP];                  // renormalized gate

// ---------------- helpers ----------------
__device__ __forceinline__ float gelu_tanh(float x) {
    float x3 = x * x * x;
    return 0.5f * x * (1.0f + tanhf(0.7978845608028654f * (x + 0.044715f * x3)));
}
__device__ __forceinline__ uint32_t smem_u32(const void* p) {
    uint32_t a;
    asm("{ .reg .u64 t; cvta.to.shared.u64 t, %1; cvt.u32.u64 %0, t; }" : "=r"(a) : "l"(p));
    return a;
}
__device__ __forceinline__ void cp_async16(uint32_t dst, const void* src) {
    asm volatile("cp.async.cg.shared.global [%0], [%1], 16;" :: "r"(dst), "l"(src));
}
__device__ __forceinline__ void cp_commit() {
    asm volatile("cp.async.commit_group;");
}
template<int N>
__device__ __forceinline__ void cp_wait() {
    asm volatile("cp.async.wait_group %0;" :: "n"(N));
}
__device__ __forceinline__ void mma_f16(float& c0, float& c1, float& c2, float& c3,
                                        uint32_t a0, uint32_t a1, uint32_t a2, uint32_t a3,
                                        uint32_t b0, uint32_t b1) {
    asm volatile(
        "mma.sync.aligned.m16n8k16.row.col.f32.f16.f16.f32 "
        "{%0,%1,%2,%3}, {%4,%5,%6,%7}, {%8,%9}, {%0,%1,%2,%3};"
        : "+f"(c0), "+f"(c1), "+f"(c2), "+f"(c3)
        : "r"(a0), "r"(a1), "r"(a2), "r"(a3), "r"(b0), "r"(b1));
}
__device__ __forceinline__ void ldsm_x4(uint32_t& r0, uint32_t& r1,
                                        uint32_t& r2, uint32_t& r3, uint32_t addr) {
    asm volatile("ldmatrix.sync.aligned.m8n8.x4.shared.b16 {%0,%1,%2,%3}, [%4];"
                 : "=r"(r0), "=r"(r1), "=r"(r2), "=r"(r3) : "r"(addr));
}

// ---------------- 1) gating ----------------
__global__ void __launch_bounds__(256) gating_kernel(
    const float* __restrict__ x, const float* __restrict__ Wg)
{
    __shared__ float sWgT[NEXP * DMODEL];
    __shared__ float sP[8][NEXP];
    for (int i = threadIdx.x; i < NEXP * DMODEL; i += blockDim.x) {
        int d = i & (DMODEL - 1);
        int e = i >> 10;
        sWgT[i] = Wg[d * NEXP + e];
    }
    __syncthreads();

    int warp = threadIdx.x >> 5;
    int lane = threadIdx.x & 31;
    int tok  = blockIdx.x * 8 + warp;

    const float* xr = x + (size_t)tok * DMODEL;
    float acc[NEXP];
    #pragma unroll
    for (int e = 0; e < NEXP; e++) acc[e] = 0.f;

    #pragma unroll 4
    for (int t = 0; t < 32; t++) {
        int d = t * 32 + lane;
        float xv = xr[d];
        #pragma unroll
        for (int e = 0; e < NEXP; e++)
            acc[e] += xv * sWgT[e * DMODEL + d];
    }
    #pragma unroll
    for (int e = 0; e < NEXP; e++) {
        #pragma unroll
        for (int off = 16; off; off >>= 1)
            acc[e] += __shfl_xor_sync(0xffffffffu, acc[e], off);
    }

    if (lane == 0) {
        float mx = acc[0];
        #pragma unroll
        for (int e = 1; e < NEXP; e++) mx = fmaxf(mx, acc[e]);
        float p[NEXP], sum = 0.f;
        #pragma unroll
        for (int e = 0; e < NEXP; e++) { p[e] = expf(acc[e] - mx); sum += p[e]; }
        float inv = 1.0f / sum;
        #pragma unroll
        for (int e = 0; e < NEXP; e++) p[e] *= inv;

        int i1 = 0; float v1 = p[0];
        #pragma unroll
        for (int e = 1; e < NEXP; e++) if (p[e] > v1) { v1 = p[e]; i1 = e; }
        int i2 = (i1 == 0) ? 1 : 0; float v2 = p[i2];
        #pragma unroll
        for (int e = 0; e < NEXP; e++)
            if (e != i1 && p[e] > v2) { v2 = p[e]; i2 = e; }

        g_idx1[tok] = i1;  g_idx2[tok] = i2;
        g_gate1[tok] = v1; g_gate2[tok] = v2;
        #pragma unroll
        for (int e = 0; e < NEXP; e++) sP[warp][e] = p[e];
    }
    __syncthreads();
    if (threadIdx.x < NEXP) {
        float s = 0.f;
        #pragma unroll
        for (int w = 0; w < 8; w++) s += sP[w][threadIdx.x];
        g_partial[blockIdx.x * NEXP + threadIdx.x] = s;
    }
}

// ---------------- 2) capacity scan + loss (32 warps: idx1 || idx2 || loss)
#define SCAN_SMEM (2 * S_TOK * 4)   // 128 KB

__global__ void __launch_bounds__(1024) scan_loss_kernel(float* loss_out)
{
    extern __shared__ int sidx[];
    int* s1 = sidx;
    int* s2 = sidx + S_TOK;
    __shared__ float sms[NEXP];

    {
        const int4* p1 = (const int4*)g_idx1;
        const int4* p2 = (const int4*)g_idx2;
        int4* q1 = (int4*)s1;
        int4* q2 = (int4*)s2;
        #pragma unroll
        for (int i = 0; i < S_TOK / 4 / 1024; i++) {
            q1[threadIdx.x + i * 1024] = p1[threadIdx.x + i * 1024];
            q2[threadIdx.x + i * 1024] = p2[threadIdx.x + i * 1024];
        }
    }
    __syncthreads();

    int warp = threadIdx.x >> 5;
    int lane = threadIdx.x & 31;
    unsigned lmask = (1u << lane) - 1u;

    if (warp < 8) {
        int e = warp;
        int cnt = 0;
        #pragma unroll 4
        for (int base = 0; base < S_TOK; base += 32) {
            int id = s1[base + lane];
            unsigned m = __ballot_sync(0xffffffffu, id == e);
            if (id == e)
                g_pos1[base + lane] = cnt + __popc(m & lmask);
            cnt += __popc(m);
        }
        if (lane == 0) g_cnt1[e] = cnt;
    } else if (warp < 16) {
        int e = warp - 8;
        int cnt2 = 0;
        #pragma unroll 4
        for (int base = 0; base < S_TOK; base += 32) {
            int id = s2[base + lane];
            unsigned m = __ballot_sync(0xffffffffu, id == e);
            if (id == e)
                g_pos2[base + lane] = cnt2 + __popc(m & lmask);
            cnt2 += __popc(m);
        }
    } else if (warp < 24) {
        int e = warp - 16;
        float s = 0.f;
        #pragma unroll 4
        for (int b = lane; b < GATE_BLOCKS; b += 32)
            s += g_partial[b * NEXP + e];
        #pragma unroll
        for (int off = 16; off; off >>= 1)
            s += __shfl_xor_sync(0xffffffffu, s, off);
        if (lane == 0) sms[e] = s;
    }
    __syncthreads();
    if (threadIdx.x == 0 && loss_out != nullptr) {
        const float invS = 1.0f / (float)S_TOK;
        float tot = 0.f;
        #pragma unroll
        for (int e2 = 0; e2 < NEXP; e2++)
            tot += (sms[e2] * invS) * ((float)g_cnt1[e2] * invS);
        *loss_out = 0.01f * (tot * 0.125f) * 64.0f;
    }
}

// ---------------- 3) zero output + slot map init (fused) ----------------
__global__ void zero_out_kernel(float4* __restrict__ out)
{
    size_t i = (size_t)blockIdx.x * blockDim.x + threadIdx.x;
    out[i] = make_float4(0.f, 0.f, 0.f, 0.f);
    if (blockIdx.x < (NEXP * CAP) / 256)
        g_slot_tok[blockIdx.x * blockDim.x + threadIdx.x] = -1;
}

// ---------------- 4) dispatch scatter + slot map (fp32 -> fp16 RN) --------
__global__ void __launch_bounds__(256) dispatch_kernel(const float* __restrict__ x)
{
    int tok = blockIdx.x;
    int i1 = g_idx1[tok], i2 = g_idx2[tok];
    int p1 = g_pos1[tok];
    int p2 = g_pos2[tok] + min(g_cnt1[i2], CAP);   // add used1 here
    float ga = g_gate1[tok], gb = g_gate2[tok];
    bool k1 = p1 < CAP, k2 = p2 < CAP;

    if (threadIdx.x == 0) {
        float a1 = k1 ? ga : 0.f;
        float a2 = k2 ? gb : 0.f;
        float denom = a1 + a2 + 1e-9f;
        if (k1) {
            g_slot_tok[i1 * CAP + p1] = tok;
            g_slot_w[i1 * CAP + p1] = a1 / denom;
        }
        if (k2) {
            g_slot_tok[i2 * CAP + p2] = tok;
            g_slot_w[i2 * CAP + p2] = a2 / denom;
        }
    }

    const float4* xr = (const float4*)(x + (size_t)tok * DMODEL);
    uint2* b1p = (uint2*)(g_bufh + ((size_t)i1 * CAP + p1) * DMODEL);
    uint2* b2p = (uint2*)(g_bufh + ((size_t)i2 * CAP + p2) * DMODEL);

    int j = threadIdx.x;
    float4 v = xr[j];
    __half2 h0 = __floats2half2_rn(v.x, v.y);
    __half2 h1 = __floats2half2_rn(v.z, v.w);
    uint2 pk = make_uint2(*(uint32_t*)&h0, *(uint32_t*)&h1);
    if (k1) b1p[j] = pk;
    if (k2) b2p[j] = pk;
}

// ---------------- 5) weight transpose fp32 -> fp16 (half2 writes) --------
// in [E][R][C] fp32 -> out [E][C][R] fp16
__global__ void __launch_bounds__(256) transpose_h_kernel(
    const float* __restrict__ in, __half* __restrict__ out, int R, int C)
{
    __shared__ float tile[32][33];
    int e = blockIdx.z;
    const float* ine = in + (size_t)e * R * C;
    __half* oute = out + (size_t)e * R * C;
    int c0 = blockIdx.x * 32, r0 = blockIdx.y * 32;
    int tx = threadIdx.x, ty = threadIdx.y;
    #pragma unroll
    for (int i = 0; i < 32; i += 8)
        tile[ty + i][tx] = ine[(size_t)(r0 + ty + i) * C + c0 + tx];
    __syncthreads();
    int rp = (tx & 15) * 2;
    int ch = tx >> 4;
    #pragma unroll
    for (int it = 0; it < 2; it++) {
        int col = ty * 4 + it * 2 + ch;
        __half2 h = __floats2half2_rn(tile[rp][col], tile[rp + 1][col]);
        *(__half2*)(oute + (size_t)(c0 + col) * R + r0 + rp) = h;
    }
}

// ---------------- 6) fp16 mma.sync grouped GEMM ---------------------------
// 128x128 block, BK=64, 4 warps (64x64 warp tile), 128 thr, 2 CTA/SM.
// Fragment double-buffering across kc chunks.
// SCATTER=0: plain store (+bias, opt gelu); SCATTER=1: slot-map atomic scatter.
#define BM 128
#define BN 128
#define BK 64
#define ROWP 72                      // 64 + 8 pad halfs; 144B stride, LDSM conflict-free
#define A_STG (BM * ROWP)            // 9216 halfs
#define B_STG (BN * ROWP)            // 9216 halfs
#define STG_H (A_STG + B_STG)        // 18432 halfs = 36864 B
#define NSTG 3
#define GEMM_SMEM (NSTG * STG_H * 2) // 110592 bytes -> 2 CTAs/SM
#define GT 128                       // GEMM threads per CTA

template<typename OutT, int DO_GELU, int SCATTER>
__global__ void __launch_bounds__(GT, 2) moe_mma_gemm(
    const __half* __restrict__ A, const __half* __restrict__ Bt,
    const float* __restrict__ bias, OutT* __restrict__ C,
    int M, int N, int K)
{
    extern __shared__ __half smemh[];
    const uint32_t sb = smem_u32(smemh);

    const int tid = threadIdx.x;
    const int lane = tid & 31;
    const int wid = tid >> 5;        // 0..3
    const int wm = wid & 1;          // warp m half (64)
    const int wn = wid >> 1;         // warp n half (64)
    const int g = lane >> 2;
    const int t4 = lane & 3;

    const int e = blockIdx.z;
    const int mbase = blockIdx.x * BM;
    const int nbase = blockIdx.y * BN;
    const __half* Ae = A + (size_t)e * M * K;
    const __half* Be = Bt + (size_t)e * N * K;

    const int ar = tid >> 3;         // row base (0..15), +16 each pass
    const int ac = tid & 7;          // chunk
    const int KT = K / BK;

    const uint32_t a_off =
        (uint32_t)((wm * 64 + (lane & 7) + ((lane >> 3) & 1) * 8) * ROWP
                   + ((lane >> 4) & 1) * 8) * 2;
    const uint32_t b_off = (uint32_t)(A_STG
                   + (wn * 64 + (lane & 7) + ((lane >> 4) & 1) * 8) * ROWP
                   + ((lane >> 3) & 1) * 8) * 2;

    auto load_stage = [&](int s, int kt) {
        uint32_t abase = sb + (uint32_t)(s * STG_H) * 2;
        uint32_t bbase = abase + A_STG * 2;
        const __half* Asrc = Ae + (size_t)mbase * K + (size_t)kt * BK;
        const __half* Bsrc = Be + (size_t)nbase * K + (size_t)kt * BK;
        #pragma unroll
        for (int t = 0; t < 8; t++) {
            int r = ar + t * 16;
            cp_async16(abase + (uint32_t)(r * ROWP + ac * 8) * 2,
                       Asrc + (size_t)r * K + ac * 8);
            cp_async16(bbase + (uint32_t)(r * ROWP + ac * 8) * 2,
                       Bsrc + (size_t)r * K + ac * 8);
        }
    };

    float acc[4][8][4];
    #pragma unroll
    for (int i = 0; i < 4; i++)
        #pragma unroll
        for (int j = 0; j < 8; j++)
            #pragma unroll
            for (int r = 0; r < 4; r++) acc[i][j][r] = 0.f;

    uint32_t afr[2][4][4], bfr[2][8][2];

    load_stage(0, 0); cp_commit();
    load_stage(1, 1); cp_commit();

    for (int kt = 0; kt < KT; kt++) {
        cp_wait<1>();
        __syncthreads();
        if (kt + 2 < KT) load_stage((kt + 2) % NSTG, kt + 2);
        cp_commit();

        uint32_t stg = sb + (uint32_t)((kt % NSTG) * STG_H) * 2;
        uint32_t a_base = stg + a_off;
        uint32_t b_base = stg + b_off;

        #pragma unroll
        for (int i = 0; i < 4; i++)
            ldsm_x4(afr[0][i][0], afr[0][i][1], afr[0][i][2], afr[0][i][3],
                    a_base + (uint32_t)(i * 16 * ROWP) * 2);
        #pragma unroll
        for (int jp = 0; jp < 4; jp++)
            ldsm_x4(bfr[0][2 * jp][0], bfr[0][2 * jp][1],
                    bfr[0][2 * jp + 1][0], bfr[0][2 * jp + 1][1],
                    b_base + (uint32_t)(jp * 16 * ROWP) * 2);

        #pragma unroll
        for (int kc = 0; kc < 4; kc++) {
            int cur = kc & 1, nxt = cur ^ 1;
            if (kc < 3) {
                #pragma unroll
                for (int i = 0; i < 4; i++)
                    ldsm_x4(afr[nxt][i][0], afr[nxt][i][1],
                            afr[nxt][i][2], afr[nxt][i][3],
                            a_base + (uint32_t)(i * 16 * ROWP + (kc + 1) * 16) * 2);
                #pragma unroll
                for (int jp = 0; jp < 4; jp++)
                    ldsm_x4(bfr[nxt][2 * jp][0], bfr[nxt][2 * jp][1],
                            bfr[nxt][2 * jp + 1][0], bfr[nxt][2 * jp + 1][1],
                            b_base + (uint32_t)(jp * 16 * ROWP + (kc + 1) * 16) * 2);
            }
            #pragma unroll
            for (int i = 0; i < 4; i++)
                #pragma unroll
                for (int j = 0; j < 8; j++)
                    mma_f16(acc[i][j][0], acc[i][j][1], acc[i][j][2], acc[i][j][3],
                            afr[cur][i][0], afr[cur][i][1],
                            afr[cur][i][2], afr[cur][i][3],
                            bfr[cur][j][0], bfr[cur][j][1]);
        }
    }

    // ---- epilogue ----
    const float* brow = bias + (size_t)e * N + nbase + wn * 64;
    if (SCATTER) {
        #pragma unroll
        for (int i = 0; i < 4; i++) {
            int slot0 = e * CAP + mbase + wm * 64 + i * 16 + g;
            int tk0 = g_slot_tok[slot0];
            int tk1 = g_slot_tok[slot0 + 8];
            float w0 = g_slot_w[slot0];
            float w1 = g_slot_w[slot0 + 8];
            float* o0 = (float*)C + (size_t)tk0 * DMODEL + nbase + wn * 64;
            float* o1 = (float*)C + (size_t)tk1 * DMODEL + nbase + wn * 64;
            #pragma unroll
            for (int j = 0; j < 8; j++) {
                int col = j * 8 + 2 * t4;
                float b0 = brow[col], b1 = brow[col + 1];
                if (tk0 >= 0) {
                    atomicAdd(o0 + col,     w0 * (acc[i][j][0] + b0));
                    atomicAdd(o0 + col + 1, w0 * (acc[i][j][1] + b1));
                }
                if (tk1 >= 0) {
                    atomicAdd(o1 + col,     w1 * (acc[i][j][2] + b0));
                    atomicAdd(o1 + col + 1, w1 * (acc[i][j][3] + b1));
                }
            }
        }
    } else {
        OutT* Cr = C + ((size_t)e * M + mbase + wm * 64) * N + nbase + wn * 64;
        #pragma unroll
        for (int i = 0; i < 4; i++) {
            #pragma unroll
            for (int j = 0; j < 8; j++) {
                int col = j * 8 + 2 * t4;
                float b0 = brow[col], b1 = brow[col + 1];
                float v0 = acc[i][j][0] + b0;
                float v1 = acc[i][j][1] + b1;
                float v2 = acc[i][j][2] + b0;
                float v3 = acc[i][j][3] + b1;
                if (DO_GELU) {
                    v0 = gelu_tanh(v0); v1 = gelu_tanh(v1);
                    v2 = gelu_tanh(v2); v3 = gelu_tanh(v3);
                }
                OutT* p0 = Cr + (size_t)(i * 16 + g) * N + col;
                OutT* p1 = Cr + (size_t)(i * 16 + g + 8) * N + col;
                if (sizeof(OutT) == 2) {
                    __half2 h0 = __floats2half2_rn(v0, v1);
                    __half2 h1 = __floats2half2_rn(v2, v3);
                    *(__half2*)p0 = h0;
                    *(__half2*)p1 = h1;
                } else {
                    *(float2*)p0 = make_float2(v0, v1);
                    *(float2*)p1 = make_float2(v2, v3);
                }
            }
        }
    }
}

// ---------------- launch ----------------
extern "C" void kernel_launch(void* const* d_in, const int* in_sizes, int n_in,
                              void* d_out, int out_size)
{
    const float* x  = (const float*)d_in[0];
    const float* Wg = (const float*)d_in[1];
    const float* W1 = (const float*)d_in[2];
    const float* b1 = (const float*)d_in[3];
    const float* W2 = (const float*)d_in[4];
    const float* b2 = (const float*)d_in[5];
    float* out = (float*)d_out;

    void *pbuf, *ph, *pw1, *pw2;
    cudaGetSymbolAddress(&pbuf, g_bufh);
    cudaGetSymbolAddress(&ph,   g_hh);
    cudaGetSymbolAddress(&pw1,  g_w1h);
    cudaGetSymbolAddress(&pw2,  g_w2h);

    cudaFuncSetAttribute((const void*)moe_mma_gemm<__half, 1, 0>,
                         cudaFuncAttributeMaxDynamicSharedMemorySize, GEMM_SMEM);
    cudaFuncSetAttribute((const void*)moe_mma_gemm<float, 0, 1>,
                         cudaFuncAttributeMaxDynamicSharedMemorySize, GEMM_SMEM);
    cudaFuncSetAttribute((const void*)scan_loss_kernel,
                         cudaFuncAttributeMaxDynamicSharedMemorySize, SCAN_SMEM);

    float* loss_ptr = (out_size > S_TOK * DMODEL) ? (out + (size_t)S_TOK * DMODEL)
                                                  : nullptr;

    // one-time host-side resources (no device memory involved)
    static cudaStream_t side = nullptr;
    static cudaEvent_t evFork = nullptr, evW1 = nullptr, evW2 = nullptr;
    if (side == nullptr) {
        cudaStreamCreateWithFlags(&side, cudaStreamNonBlocking);
        cudaEventCreateWithFlags(&evFork, cudaEventDisableTiming);
        cudaEventCreateWithFlags(&evW1, cudaEventDisableTiming);
        cudaEventCreateWithFlags(&evW2, cudaEventDisableTiming);
    }

    // ---- fork: weight transposes on side stream ----
    cudaEventRecord(evFork, 0);
    cudaStreamWaitEvent(side, evFork, 0);
    transpose_h_kernel<<<dim3(HFFN / 32, DMODEL / 32, NEXP), dim3(32, 8), 0, side>>>(
        W1, (__half*)pw1, DMODEL, HFFN);
    cudaEventRecord(evW1, side);
    transpose_h_kernel<<<dim3(DMODEL / 32, HFFN / 32, NEXP), dim3(32, 8), 0, side>>>(
        W2, (__half*)pw2, HFFN, DMODEL);
    cudaEventRecord(evW2, side);

    // ---- main stream: gating chain (overlaps transpose W1) ----
    gating_kernel<<<GATE_BLOCKS, 256>>>(x, Wg);
    scan_loss_kernel<<<1, 1024, SCAN_SMEM>>>(loss_ptr);
    zero_out_kernel<<<(S_TOK * DMODEL / 4) / 256, 256>>>((float4*)out);
    dispatch_kernel<<<S_TOK, 256>>>(x);

    // GEMM1 needs W1^T + dispatch
    cudaStreamWaitEvent(0, evW1, 0);
    moe_mma_gemm<__half, 1, 0><<<dim3(CAP / BM, HFFN / BN, NEXP), GT, GEMM_SMEM>>>(
        (const __half*)pbuf, (const __half*)pw1, b1, (__half*)ph,
        CAP, HFFN, DMODEL);

    // GEMM2 needs W2^T (transpose W2 overlapped GEMM1) + h
    cudaStreamWaitEvent(0, evW2, 0);
    moe_mma_gemm<float, 0, 1><<<dim3(CAP / BM, DMODEL / BN, NEXP), GT, GEMM_SMEM>>>(
        (const __half*)ph, (const __half*)pw2, b2, out,
        CAP, DMODEL, HFFN);
}

// round 17
// speedup vs baseline: 1.0090x; 1.0090x over previous
#include <cuda_runtime.h>
#include <cuda_fp16.h>
#include <math.h>
#include <stdint.h>

// ---------------- problem constants ----------------
#define S_TOK   16384          // B*N
#define DMODEL  1024
#define NEXP    8
#define HFFN    4096
#define CAP     2560           // int(S*1.25/E)
#define GATE_BLOCKS (S_TOK/8)

// ---------------- device scratch (allocation-free rule) ----------------
__device__ __half g_bufh[NEXP * CAP * DMODEL];            // 42 MB  dispatch fp16
__device__ __half g_hh  [(size_t)NEXP * CAP * HFFN];      // 168 MB hidden fp16
__device__ __half g_w1h [(size_t)NEXP * HFFN * DMODEL];   // 67 MB  W1^T [E][H][D]
__device__ __half g_w2h [(size_t)NEXP * DMODEL * HFFN];   // 67 MB  W2^T [E][D][H]
__device__ float g_gate1[S_TOK];
__device__ float g_gate2[S_TOK];
__device__ int   g_idx1[S_TOK];
__device__ int   g_idx2[S_TOK];
__device__ int   g_pos1[S_TOK];
__device__ int   g_pos2[S_TOK];      // RAW top-2 prefix (used1 added in dispatch)
__device__ float g_partial[GATE_BLOCKS * NEXP];
__device__ int   g_cnt1[NEXP];
__device__ int   g_slot_tok[NEXP * CAP];                  // token id or -1
__device__ float g_slot_w  [NEXP * CAP];                  // renormalized gate

// ---------------- helpers ----------------
__device__ __forceinline__ float gelu_tanh(float x) {
    float x3 = x * x * x;
    return 0.5f * x * (1.0f + tanhf(0.7978845608028654f * (x + 0.044715f * x3)));
}
__device__ __forceinline__ uint32_t smem_u32(const void* p) {
    uint32_t a;
    asm("{ .reg .u64 t; cvta.to.shared.u64 t, %1; cvt.u32.u64 %0, t; }" : "=r"(a) : "l"(p));
    return a;
}
__device__ __forceinline__ void cp_async16(uint32_t dst, const void* src) {
    asm volatile("cp.async.cg.shared.global [%0], [%1], 16;" :: "r"(dst), "l"(src));
}
__device__ __forceinline__ void cp_commit() {
    asm volatile("cp.async.commit_group;");
}
template<int N>
__device__ __forceinline__ void cp_wait() {
    asm volatile("cp.async.wait_group %0;" :: "n"(N));
}
__device__ __forceinline__ void mma_f16(float& c0, float& c1, float& c2, float& c3,
                                        uint32_t a0, uint32_t a1, uint32_t a2, uint32_t a3,
                                        uint32_t b0, uint32_t b1) {
    asm volatile(
        "mma.sync.aligned.m16n8k16.row.col.f32.f16.f16.f32 "
        "{%0,%1,%2,%3}, {%4,%5,%6,%7}, {%8,%9}, {%0,%1,%2,%3};"
        : "+f"(c0), "+f"(c1), "+f"(c2), "+f"(c3)
        : "r"(a0), "r"(a1), "r"(a2), "r"(a3), "r"(b0), "r"(b1));
}
__device__ __forceinline__ void ldsm_x4(uint32_t& r0, uint32_t& r1,
                                        uint32_t& r2, uint32_t& r3, uint32_t addr) {
    asm volatile("ldmatrix.sync.aligned.m8n8.x4.shared.b16 {%0,%1,%2,%3}, [%4];"
                 : "=r"(r0), "=r"(r1), "=r"(r2), "=r"(r3) : "r"(addr));
}

// ---------------- 1) gating ----------------
__global__ void __launch_bounds__(256) gating_kernel(
    const float* __restrict__ x, const float* __restrict__ Wg)
{
    __shared__ float sWgT[NEXP * DMODEL];
    __shared__ float sP[8][NEXP];
    for (int i = threadIdx.x; i < NEXP * DMODEL; i += blockDim.x) {
        int d = i & (DMODEL - 1);
        int e = i >> 10;
        sWgT[i] = Wg[d * NEXP + e];
    }
    __syncthreads();

    int warp = threadIdx.x >> 5;
    int lane = threadIdx.x & 31;
    int tok  = blockIdx.x * 8 + warp;

    const float* xr = x + (size_t)tok * DMODEL;
    float acc[NEXP];
    #pragma unroll
    for (int e = 0; e < NEXP; e++) acc[e] = 0.f;

    #pragma unroll 4
    for (int t = 0; t < 32; t++) {
        int d = t * 32 + lane;
        float xv = xr[d];
        #pragma unroll
        for (int e = 0; e < NEXP; e++)
            acc[e] += xv * sWgT[e * DMODEL + d];
    }
    #pragma unroll
    for (int e = 0; e < NEXP; e++) {
        #pragma unroll
        for (int off = 16; off; off >>= 1)
            acc[e] += __shfl_xor_sync(0xffffffffu, acc[e], off);
    }

    if (lane == 0) {
        float mx = acc[0];
        #pragma unroll
        for (int e = 1; e < NEXP; e++) mx = fmaxf(mx, acc[e]);
        float p[NEXP], sum = 0.f;
        #pragma unroll
        for (int e = 0; e < NEXP; e++) { p[e] = expf(acc[e] - mx); sum += p[e]; }
        float inv = 1.0f / sum;
        #pragma unroll
        for (int e = 0; e < NEXP; e++) p[e] *= inv;

        int i1 = 0; float v1 = p[0];
        #pragma unroll
        for (int e = 1; e < NEXP; e++) if (p[e] > v1) { v1 = p[e]; i1 = e; }
        int i2 = (i1 == 0) ? 1 : 0; float v2 = p[i2];
        #pragma unroll
        for (int e = 0; e < NEXP; e++)
            if (e != i1 && p[e] > v2) { v2 = p[e]; i2 = e; }

        g_idx1[tok] = i1;  g_idx2[tok] = i2;
        g_gate1[tok] = v1; g_gate2[tok] = v2;
        #pragma unroll
        for (int e = 0; e < NEXP; e++) sP[warp][e] = p[e];
    }
    __syncthreads();
    if (threadIdx.x < NEXP) {
        float s = 0.f;
        #pragma unroll
        for (int w = 0; w < 8; w++) s += sP[w][threadIdx.x];
        g_partial[blockIdx.x * NEXP + threadIdx.x] = s;
    }
}

// ---------------- 2) capacity scan + loss + slot init (32 warps) ---------
#define SCAN_SMEM (2 * S_TOK * 4)   // 128 KB

__global__ void __launch_bounds__(1024) scan_loss_kernel(float* loss_out)
{
    extern __shared__ int sidx[];
    int* s1 = sidx;
    int* s2 = sidx + S_TOK;
    __shared__ float sms[NEXP];

    {
        const int4* p1 = (const int4*)g_idx1;
        const int4* p2 = (const int4*)g_idx2;
        int4* q1 = (int4*)s1;
        int4* q2 = (int4*)s2;
        #pragma unroll
        for (int i = 0; i < S_TOK / 4 / 1024; i++) {
            q1[threadIdx.x + i * 1024] = p1[threadIdx.x + i * 1024];
            q2[threadIdx.x + i * 1024] = p2[threadIdx.x + i * 1024];
        }
    }
    __syncthreads();

    int warp = threadIdx.x >> 5;
    int lane = threadIdx.x & 31;
    unsigned lmask = (1u << lane) - 1u;

    if (warp < 8) {
        int e = warp;
        int cnt = 0;
        #pragma unroll 4
        for (int base = 0; base < S_TOK; base += 32) {
            int id = s1[base + lane];
            unsigned m = __ballot_sync(0xffffffffu, id == e);
            if (id == e)
                g_pos1[base + lane] = cnt + __popc(m & lmask);
            cnt += __popc(m);
        }
        if (lane == 0) g_cnt1[e] = cnt;
    } else if (warp < 16) {
        int e = warp - 8;
        int cnt2 = 0;
        #pragma unroll 4
        for (int base = 0; base < S_TOK; base += 32) {
            int id = s2[base + lane];
            unsigned m = __ballot_sync(0xffffffffu, id == e);
            if (id == e)
                g_pos2[base + lane] = cnt2 + __popc(m & lmask);
            cnt2 += __popc(m);
        }
    } else if (warp < 24) {
        int e = warp - 16;
        float s = 0.f;
        #pragma unroll 4
        for (int b = lane; b < GATE_BLOCKS; b += 32)
            s += g_partial[b * NEXP + e];
        #pragma unroll
        for (int off = 16; off; off >>= 1)
            s += __shfl_xor_sync(0xffffffffu, s, off);
        if (lane == 0) sms[e] = s;
    } else {
        // warps 24-31: slot map init (runs before dispatch; same-stream order)
        int t = (warp - 24) * 32 + lane;        // 0..255
        #pragma unroll
        for (int i = 0; i < NEXP * CAP / 256; i++)
            g_slot_tok[t + i * 256] = -1;
    }
    __syncthreads();
    if (threadIdx.x == 0 && loss_out != nullptr) {
        const float invS = 1.0f / (float)S_TOK;
        float tot = 0.f;
        #pragma unroll
        for (int e2 = 0; e2 < NEXP; e2++)
            tot += (sms[e2] * invS) * ((float)g_cnt1[e2] * invS);
        *loss_out = 0.01f * (tot * 0.125f) * 64.0f;
    }
}

// ---------------- 3) zero output (atomic accumulate target) ---------------
__global__ void zero_out_kernel(float4* __restrict__ out)
{
    size_t i = (size_t)blockIdx.x * blockDim.x + threadIdx.x;
    out[i] = make_float4(0.f, 0.f, 0.f, 0.f);
}

// ---------------- 4) dispatch scatter + slot map (fp32 -> fp16 RN) --------
__global__ void __launch_bounds__(256) dispatch_kernel(const float* __restrict__ x)
{
    int tok = blockIdx.x;
    int i1 = g_idx1[tok], i2 = g_idx2[tok];
    int p1 = g_pos1[tok];
    int p2 = g_pos2[tok] + min(g_cnt1[i2], CAP);   // add used1 here
    float ga = g_gate1[tok], gb = g_gate2[tok];
    bool k1 = p1 < CAP, k2 = p2 < CAP;

    if (threadIdx.x == 0) {
        float a1 = k1 ? ga : 0.f;
        float a2 = k2 ? gb : 0.f;
        float denom = a1 + a2 + 1e-9f;
        if (k1) {
            g_slot_tok[i1 * CAP + p1] = tok;
            g_slot_w[i1 * CAP + p1] = a1 / denom;
        }
        if (k2) {
            g_slot_tok[i2 * CAP + p2] = tok;
            g_slot_w[i2 * CAP + p2] = a2 / denom;
        }
    }

    const float4* xr = (const float4*)(x + (size_t)tok * DMODEL);
    uint2* b1p = (uint2*)(g_bufh + ((size_t)i1 * CAP + p1) * DMODEL);
    uint2* b2p = (uint2*)(g_bufh + ((size_t)i2 * CAP + p2) * DMODEL);

    int j = threadIdx.x;
    float4 v = xr[j];
    __half2 h0 = __floats2half2_rn(v.x, v.y);
    __half2 h1 = __floats2half2_rn(v.z, v.w);
    uint2 pk = make_uint2(*(uint32_t*)&h0, *(uint32_t*)&h1);
    if (k1) b1p[j] = pk;
    if (k2) b2p[j] = pk;
}

// ---------------- 5) weight transpose fp32 -> fp16 (half2 writes) --------
// in [E][R][C] fp32 -> out [E][C][R] fp16
__global__ void __launch_bounds__(256) transpose_h_kernel(
    const float* __restrict__ in, __half* __restrict__ out, int R, int C)
{
    __shared__ float tile[32][33];
    int e = blockIdx.z;
    const float* ine = in + (size_t)e * R * C;
    __half* oute = out + (size_t)e * R * C;
    int c0 = blockIdx.x * 32, r0 = blockIdx.y * 32;
    int tx = threadIdx.x, ty = threadIdx.y;
    #pragma unroll
    for (int i = 0; i < 32; i += 8)
        tile[ty + i][tx] = ine[(size_t)(r0 + ty + i) * C + c0 + tx];
    __syncthreads();
    int rp = (tx & 15) * 2;
    int ch = tx >> 4;
    #pragma unroll
    for (int it = 0; it < 2; it++) {
        int col = ty * 4 + it * 2 + ch;
        __half2 h = __floats2half2_rn(tile[rp][col], tile[rp + 1][col]);
        *(__half2*)(oute + (size_t)(c0 + col) * R + r0 + rp) = h;
    }
}

// ---------------- 6) fp16 mma.sync grouped GEMM ---------------------------
// 128x128 block, BK=64, 4 warps (64x64 warp tile), 128 thr, 2 CTA/SM.
// Fragment double-buffering across kc chunks.
// SCATTER=0: plain store (+bias, opt gelu); SCATTER=1: slot-map atomic scatter.
#define BM 128
#define BN 128
#define BK 64
#define ROWP 72                      // 64 + 8 pad halfs; 144B stride, LDSM conflict-free
#define A_STG (BM * ROWP)            // 9216 halfs
#define B_STG (BN * ROWP)            // 9216 halfs
#define STG_H (A_STG + B_STG)        // 18432 halfs = 36864 B
#define NSTG 3
#define GEMM_SMEM (NSTG * STG_H * 2) // 110592 bytes -> 2 CTAs/SM
#define GT 128                       // GEMM threads per CTA

template<typename OutT, int DO_GELU, int SCATTER>
__global__ void __launch_bounds__(GT, 2) moe_mma_gemm(
    const __half* __restrict__ A, const __half* __restrict__ Bt,
    const float* __restrict__ bias, OutT* __restrict__ C,
    int M, int N, int K)
{
    extern __shared__ __half smemh[];
    const uint32_t sb = smem_u32(smemh);

    const int tid = threadIdx.x;
    const int lane = tid & 31;
    const int wid = tid >> 5;        // 0..3
    const int wm = wid & 1;          // warp m half (64)
    const int wn = wid >> 1;         // warp n half (64)
    const int g = lane >> 2;
    const int t4 = lane & 3;

    const int e = blockIdx.z;
    const int mbase = blockIdx.x * BM;
    const int nbase = blockIdx.y * BN;
    const __half* Ae = A + (size_t)e * M * K;
    const __half* Be = Bt + (size_t)e * N * K;

    const int ar = tid >> 3;         // row base (0..15), +16 each pass
    const int ac = tid & 7;          // chunk
    const int KT = K / BK;

    const uint32_t a_off =
        (uint32_t)((wm * 64 + (lane & 7) + ((lane >> 3) & 1) * 8) * ROWP
                   + ((lane >> 4) & 1) * 8) * 2;
    const uint32_t b_off = (uint32_t)(A_STG
                   + (wn * 64 + (lane & 7) + ((lane >> 4) & 1) * 8) * ROWP
                   + ((lane >> 3) & 1) * 8) * 2;

    auto load_stage = [&](int s, int kt) {
        uint32_t abase = sb + (uint32_t)(s * STG_H) * 2;
        uint32_t bbase = abase + A_STG * 2;
        const __half* Asrc = Ae + (size_t)mbase * K + (size_t)kt * BK;
        const __half* Bsrc = Be + (size_t)nbase * K + (size_t)kt * BK;
        #pragma unroll
        for (int t = 0; t < 8; t++) {
            int r = ar + t * 16;
            cp_async16(abase + (uint32_t)(r * ROWP + ac * 8) * 2,
                       Asrc + (size_t)r * K + ac * 8);
            cp_async16(bbase + (uint32_t)(r * ROWP + ac * 8) * 2,
                       Bsrc + (size_t)r * K + ac * 8);
        }
    };

    float acc[4][8][4];
    #pragma unroll
    for (int i = 0; i < 4; i++)
        #pragma unroll
        for (int j = 0; j < 8; j++)
            #pragma unroll
            for (int r = 0; r < 4; r++) acc[i][j][r] = 0.f;

    uint32_t afr[2][4][4], bfr[2][8][2];

    load_stage(0, 0); cp_commit();
    load_stage(1, 1); cp_commit();

    for (int kt = 0; kt < KT; kt++) {
        cp_wait<1>();
        __syncthreads();
        if (kt + 2 < KT) load_stage((kt + 2) % NSTG, kt + 2);
        cp_commit();

        uint32_t stg = sb + (uint32_t)((kt % NSTG) * STG_H) * 2;
        uint32_t a_base = stg + a_off;
        uint32_t b_base = stg + b_off;

        #pragma unroll
        for (int i = 0; i < 4; i++)
            ldsm_x4(afr[0][i][0], afr[0][i][1], afr[0][i][2], afr[0][i][3],
                    a_base + (uint32_t)(i * 16 * ROWP) * 2);
        #pragma unroll
        for (int jp = 0; jp < 4; jp++)
            ldsm_x4(bfr[0][2 * jp][0], bfr[0][2 * jp][1],
                    bfr[0][2 * jp + 1][0], bfr[0][2 * jp + 1][1],
                    b_base + (uint32_t)(jp * 16 * ROWP) * 2);

        #pragma unroll
        for (int kc = 0; kc < 4; kc++) {
            int cur = kc & 1, nxt = cur ^ 1;
            if (kc < 3) {
                #pragma unroll
                for (int i = 0; i < 4; i++)
                    ldsm_x4(afr[nxt][i][0], afr[nxt][i][1],
                            afr[nxt][i][2], afr[nxt][i][3],
                            a_base + (uint32_t)(i * 16 * ROWP + (kc + 1) * 16) * 2);
                #pragma unroll
                for (int jp = 0; jp < 4; jp++)
                    ldsm_x4(bfr[nxt][2 * jp][0], bfr[nxt][2 * jp][1],
                            bfr[nxt][2 * jp + 1][0], bfr[nxt][2 * jp + 1][1],
                            b_base + (uint32_t)(jp * 16 * ROWP + (kc + 1) * 16) * 2);
            }
            #pragma unroll
            for (int i = 0; i < 4; i++)
                #pragma unroll
                for (int j = 0; j < 8; j++)
                    mma_f16(acc[i][j][0], acc[i][j][1], acc[i][j][2], acc[i][j][3],
                            afr[cur][i][0], afr[cur][i][1],
                            afr[cur][i][2], afr[cur][i][3],
                            bfr[cur][j][0], bfr[cur][j][1]);
        }
    }

    // ---- epilogue ----
    const float* brow = bias + (size_t)e * N + nbase + wn * 64;
    if (SCATTER) {
        #pragma unroll
        for (int i = 0; i < 4; i++) {
            int slot0 = e * CAP + mbase + wm * 64 + i * 16 + g;
            int tk0 = g_slot_tok[slot0];
            int tk1 = g_slot_tok[slot0 + 8];
            float w0 = g_slot_w[slot0];
            float w1 = g_slot_w[slot0 + 8];
            float* o0 = (float*)C + (size_t)tk0 * DMODEL + nbase + wn * 64;
            float* o1 = (float*)C + (size_t)tk1 * DMODEL + nbase + wn * 64;
            #pragma unroll
            for (int j = 0; j < 8; j++) {
                int col = j * 8 + 2 * t4;
                float b0 = brow[col], b1 = brow[col + 1];
                if (tk0 >= 0) {
                    atomicAdd(o0 + col,     w0 * (acc[i][j][0] + b0));
                    atomicAdd(o0 + col + 1, w0 * (acc[i][j][1] + b1));
                }
                if (tk1 >= 0) {
                    atomicAdd(o1 + col,     w1 * (acc[i][j][2] + b0));
                    atomicAdd(o1 + col + 1, w1 * (acc[i][j][3] + b1));
                }
            }
        }
    } else {
        OutT* Cr = C + ((size_t)e * M + mbase + wm * 64) * N + nbase + wn * 64;
        #pragma unroll
        for (int i = 0; i < 4; i++) {
            #pragma unroll
            for (int j = 0; j < 8; j++) {
                int col = j * 8 + 2 * t4;
                float b0 = brow[col], b1 = brow[col + 1];
                float v0 = acc[i][j][0] + b0;
                float v1 = acc[i][j][1] + b1;
                float v2 = acc[i][j][2] + b0;
                float v3 = acc[i][j][3] + b1;
                if (DO_GELU) {
                    v0 = gelu_tanh(v0); v1 = gelu_tanh(v1);
                    v2 = gelu_tanh(v2); v3 = gelu_tanh(v3);
                }
                OutT* p0 = Cr + (size_t)(i * 16 + g) * N + col;
                OutT* p1 = Cr + (size_t)(i * 16 + g + 8) * N + col;
                if (sizeof(OutT) == 2) {
                    __half2 h0 = __floats2half2_rn(v0, v1);
                    __half2 h1 = __floats2half2_rn(v2, v3);
                    *(__half2*)p0 = h0;
                    *(__half2*)p1 = h1;
                } else {
                    *(float2*)p0 = make_float2(v0, v1);
                    *(float2*)p1 = make_float2(v2, v3);
                }
            }
        }
    }
}

// ---------------- launch ----------------
extern "C" void kernel_launch(void* const* d_in, const int* in_sizes, int n_in,
                              void* d_out, int out_size)
{
    const float* x  = (const float*)d_in[0];
    const float* Wg = (const float*)d_in[1];
    const float* W1 = (const float*)d_in[2];
    const float* b1 = (const float*)d_in[3];
    const float* W2 = (const float*)d_in[4];
    const float* b2 = (const float*)d_in[5];
    float* out = (float*)d_out;

    void *pbuf, *ph, *pw1, *pw2;
    cudaGetSymbolAddress(&pbuf, g_bufh);
    cudaGetSymbolAddress(&ph,   g_hh);
    cudaGetSymbolAddress(&pw1,  g_w1h);
    cudaGetSymbolAddress(&pw2,  g_w2h);

    cudaFuncSetAttribute((const void*)moe_mma_gemm<__half, 1, 0>,
                         cudaFuncAttributeMaxDynamicSharedMemorySize, GEMM_SMEM);
    cudaFuncSetAttribute((const void*)moe_mma_gemm<float, 0, 1>,
                         cudaFuncAttributeMaxDynamicSharedMemorySize, GEMM_SMEM);
    cudaFuncSetAttribute((const void*)scan_loss_kernel,
                         cudaFuncAttributeMaxDynamicSharedMemorySize, SCAN_SMEM);

    float* loss_ptr = (out_size > S_TOK * DMODEL) ? (out + (size_t)S_TOK * DMODEL)
                                                  : nullptr;

    // one-time host-side resources (no device memory involved)
    static cudaStream_t side = nullptr;
    static cudaEvent_t evFork = nullptr, evW1 = nullptr, evZ = nullptr;
    if (side == nullptr) {
        cudaStreamCreateWithFlags(&side, cudaStreamNonBlocking);
        cudaEventCreateWithFlags(&evFork, cudaEventDisableTiming);
        cudaEventCreateWithFlags(&evW1, cudaEventDisableTiming);
        cudaEventCreateWithFlags(&evZ, cudaEventDisableTiming);
    }

    // ---- fork: transposes + out-zeroing on side stream ----
    cudaEventRecord(evFork, 0);
    cudaStreamWaitEvent(side, evFork, 0);
    transpose_h_kernel<<<dim3(HFFN / 32, DMODEL / 32, NEXP), dim3(32, 8), 0, side>>>(
        W1, (__half*)pw1, DMODEL, HFFN);
    cudaEventRecord(evW1, side);
    transpose_h_kernel<<<dim3(DMODEL / 32, HFFN / 32, NEXP), dim3(32, 8), 0, side>>>(
        W2, (__half*)pw2, HFFN, DMODEL);
    zero_out_kernel<<<(S_TOK * DMODEL / 4) / 256, 256, 0, side>>>((float4*)out);
    cudaEventRecord(evZ, side);

    // ---- main stream: gating chain (overlaps transpose W1) ----
    gating_kernel<<<GATE_BLOCKS, 256>>>(x, Wg);
    scan_loss_kernel<<<1, 1024, SCAN_SMEM>>>(loss_ptr);   // also inits slot map
    dispatch_kernel<<<S_TOK, 256>>>(x);

    // GEMM1 needs W1^T + dispatch
    cudaStreamWaitEvent(0, evW1, 0);
    moe_mma_gemm<__half, 1, 0><<<dim3(CAP / BM, HFFN / BN, NEXP), GT, GEMM_SMEM>>>(
        (const __half*)pbuf, (const __half*)pw1, b1, (__half*)ph,
        CAP, HFFN, DMODEL);

    // GEMM2 needs W2^T + zeroed out (side-stream order: W2 then zero -> evZ)
    cudaStreamWaitEvent(0, evZ, 0);
    moe_mma_gemm<float, 0, 1><<<dim3(CAP / BM, DMODEL / BN, NEXP), GT, GEMM_SMEM>>>(
        (const __half*)ph, (const __half*)pw2, b2, out,
        CAP, DMODEL, HFFN);
}